// round 2
// baseline (speedup 1.0000x reference)
#include <cuda_runtime.h>

#define NN 100000
#define EE 800000
#define DD 96

// ---------------- device scratch (allocation-free workaround) ----------------
__device__ float g_h[NN * DD];        // GEMM output of current layer
__device__ float g_mid[NN * DD];      // layer-1 aggregated output
__device__ float g_alpha_s[NN];
__device__ float g_alpha_d[NN];
__device__ float g_w[EE];             // edge weights in CSR (sorted) order
__device__ int   g_src[EE];
__device__ int   g_dst[EE];
__device__ int   g_src_sorted[EE];
__device__ int   g_dst_sorted[EE];
__device__ int   g_counts[NN];
__device__ int   g_cursor[NN];
__device__ int   g_offsets[NN + 1];
__device__ int   g_bsums[128];
__device__ int   g_is64;

// ---------------- edge_index layout detection (int32 vs int64) --------------
// src begins with arange(N): int32 words [1],[3],[5] are 1,3,5; for little-endian
// int64 they are the zero high words.
__global__ void k_detect(const int* __restrict__ ei) {
    if (threadIdx.x == 0)
        g_is64 = (ei[1] == 0 && ei[3] == 0 && ei[5] == 0) ? 1 : 0;
}

__global__ void k_extract(const int* __restrict__ ei) {
    int e = blockIdx.x * blockDim.x + threadIdx.x;
    if (e >= EE) return;
    int s, d;
    if (g_is64) { s = ei[2 * e];  d = ei[2 * (EE + e)]; }
    else        { s = ei[e];      d = ei[EE + e]; }
    g_src[e] = s;
    g_dst[e] = d;
}

// ---------------- CSR build ----------------
__global__ void k_zero() {
    int i = blockIdx.x * blockDim.x + threadIdx.x;
    if (i < NN) { g_counts[i] = 0; g_cursor[i] = 0; }
}

__global__ void k_count() {
    int e = blockIdx.x * blockDim.x + threadIdx.x;
    if (e < EE) atomicAdd(&g_counts[g_src[e]], 1);
}

// block-level exclusive scan (1024 per block)
__global__ void k_scanA() {
    __shared__ int buf[1024];
    int tid = threadIdx.x;
    int i = blockIdx.x * 1024 + tid;
    int v = (i < NN) ? g_counts[i] : 0;
    buf[tid] = v;
    __syncthreads();
    #pragma unroll
    for (int off = 1; off < 1024; off <<= 1) {
        int t = (tid >= off) ? buf[tid - off] : 0;
        __syncthreads();
        buf[tid] += t;
        __syncthreads();
    }
    if (i < NN) g_offsets[i] = buf[tid] - v;       // exclusive within block
    if (tid == 1023) g_bsums[blockIdx.x] = buf[1023];
}

__global__ void k_scanB(int nblocks) {
    __shared__ int buf[128];
    int tid = threadIdx.x;
    int v = (tid < nblocks) ? g_bsums[tid] : 0;
    buf[tid] = v;
    __syncthreads();
    #pragma unroll
    for (int off = 1; off < 128; off <<= 1) {
        int t = (tid >= off) ? buf[tid - off] : 0;
        __syncthreads();
        buf[tid] += t;
        __syncthreads();
    }
    if (tid < nblocks) g_bsums[tid] = buf[tid] - v;  // exclusive
}

__global__ void k_scanC() {
    int tid = threadIdx.x;
    int i = blockIdx.x * 1024 + tid;
    if (i < NN) g_offsets[i] += g_bsums[blockIdx.x];
    if (i == 0) g_offsets[NN] = EE;
}

__global__ void k_scatter() {
    int e = blockIdx.x * blockDim.x + threadIdx.x;
    if (e >= EE) return;
    int s = g_src[e];
    int slot = g_offsets[s] + atomicAdd(&g_cursor[s], 1);
    g_dst_sorted[slot] = g_dst[e];
    g_src_sorted[slot] = s;
}

// ---------------- GEMM: H = X @ W  (N x 96 @ 96 x 96) ----------------
// BM=64 rows/block, full 96 cols, full K=96 resident. 256 threads, 4x6 per thread.
__global__ void k_gemm(const float* __restrict__ X, const float* __restrict__ W,
                       float* __restrict__ H) {
    extern __shared__ float sm[];
    float* Ws = sm;                 // 96*96
    float* Xs = sm + 96 * 96;       // 64*97 (padded)
    int tid = threadIdx.x;

    for (int i = tid; i < (96 * 96) / 4; i += 256)
        ((float4*)Ws)[i] = ((const float4*)W)[i];

    int row0 = blockIdx.x * 64;
    for (int i = tid; i < 64 * 24; i += 256) {
        int r = i / 24, c4 = i % 24;
        int gr = row0 + r;
        float4 v = (gr < NN) ? ((const float4*)(X + (size_t)gr * 96))[c4]
                             : make_float4(0.f, 0.f, 0.f, 0.f);
        float* p = &Xs[r * 97 + c4 * 4];
        p[0] = v.x; p[1] = v.y; p[2] = v.z; p[3] = v.w;
    }
    __syncthreads();

    int tx = tid & 15, ty = tid >> 4;
    float acc[4][6];
    #pragma unroll
    for (int r = 0; r < 4; r++)
        #pragma unroll
        for (int c = 0; c < 6; c++) acc[r][c] = 0.f;

    const float* xb = &Xs[(ty * 4) * 97];
    const float* wb = &Ws[tx * 6];

    #pragma unroll 4
    for (int k = 0; k < 96; k++) {
        float xv[4];
        #pragma unroll
        for (int r = 0; r < 4; r++) xv[r] = xb[r * 97 + k];
        float2 wA = *(const float2*)&wb[k * 96];
        float2 wB = *(const float2*)&wb[k * 96 + 2];
        float2 wC = *(const float2*)&wb[k * 96 + 4];
        float wv[6] = {wA.x, wA.y, wB.x, wB.y, wC.x, wC.y};
        #pragma unroll
        for (int r = 0; r < 4; r++)
            #pragma unroll
            for (int c = 0; c < 6; c++)
                acc[r][c] = fmaf(xv[r], wv[c], acc[r][c]);
    }

    #pragma unroll
    for (int r = 0; r < 4; r++) {
        int gr = row0 + ty * 4 + r;
        if (gr < NN) {
            float* o = H + (size_t)gr * 96 + tx * 6;
            *(float2*)&o[0] = make_float2(acc[r][0], acc[r][1]);
            *(float2*)&o[2] = make_float2(acc[r][2], acc[r][3]);
            *(float2*)&o[4] = make_float2(acc[r][4], acc[r][5]);
        }
    }
}

// ---------------- per-node alpha: as = h.a[:96], ad = h.a[96:] ----------------
__global__ void k_alpha(const float* __restrict__ h, const float* __restrict__ a) {
    int t = blockIdx.x * blockDim.x + threadIdx.x;
    int n = t >> 5, lane = t & 31;
    if (n >= NN) return;
    const float* hr = h + (size_t)n * DD;
    float h0 = hr[lane], h1 = hr[lane + 32], h2 = hr[lane + 64];
    float as = h0 * a[lane] + h1 * a[lane + 32] + h2 * a[lane + 64];
    float ad = h0 * a[96 + lane] + h1 * a[128 + lane] + h2 * a[160 + lane];
    #pragma unroll
    for (int o = 16; o; o >>= 1) {
        as += __shfl_xor_sync(0xffffffffu, as, o);
        ad += __shfl_xor_sync(0xffffffffu, ad, o);
    }
    if (!lane) { g_alpha_s[n] = as; g_alpha_d[n] = ad; }
}

// ---------------- per-edge weight (in CSR order) ----------------
__global__ void k_edgew() {
    int i = blockIdx.x * blockDim.x + threadIdx.x;
    if (i >= EE) return;
    float s = g_alpha_s[g_src_sorted[i]] + g_alpha_d[g_dst_sorted[i]];
    float lr = (s > 0.f) ? s : 0.01f * s;     // leaky_relu
    g_w[i] = __expf(-lr);
}

// ---------------- aggregation: warp per node, gather over CSR row ------------
__global__ void k_agg(const float* __restrict__ h, float* __restrict__ out, int relu) {
    int t = blockIdx.x * blockDim.x + threadIdx.x;
    int n = t >> 5, lane = t & 31;
    if (n >= NN) return;
    int j = g_offsets[n], e = g_offsets[n + 1];
    float aw = 0.f, a0 = 0.f, a1 = 0.f, a2 = 0.f;
    for (; j < e; j++) {
        int d = g_dst_sorted[j];
        float w = g_w[j];
        const float* hr = h + (size_t)d * DD;
        aw += w;
        a0 = fmaf(w, hr[lane], a0);
        a1 = fmaf(w, hr[lane + 32], a1);
        a2 = fmaf(w, hr[lane + 64], a2);
    }
    float inv = 1.0f / aw;
    a0 *= inv; a1 *= inv; a2 *= inv;
    if (relu) {
        a0 = fmaxf(a0, 0.f); a1 = fmaxf(a1, 0.f); a2 = fmaxf(a2, 0.f);
    }
    float* o = out + (size_t)n * DD;
    o[lane] = a0; o[lane + 32] = a1; o[lane + 64] = a2;
}

// ---------------- launch ----------------
extern "C" void kernel_launch(void* const* d_in, const int* in_sizes, int n_in,
                              void* d_out, int out_size) {
    const int*   ei = (const int*)d_in[0];
    const float* x  = (const float*)d_in[1];
    const float* W1 = (const float*)d_in[2];
    const float* a1 = (const float*)d_in[3];
    const float* W2 = (const float*)d_in[4];
    const float* a2 = (const float*)d_in[5];
    float* out = (float*)d_out;

    void *ph, *pmid;
    cudaGetSymbolAddress(&ph, g_h);
    cudaGetSymbolAddress(&pmid, g_mid);
    float* h   = (float*)ph;
    float* mid = (float*)pmid;

    const int TB = 256;
    const int eb = (EE + TB - 1) / TB;
    const int nb = (NN + TB - 1) / TB;
    const int scan_blocks = (NN + 1023) / 1024;     // 98
    const int gemm_blocks = (NN + 63) / 64;         // 1563
    const int warp_blocks = (NN * 32 + TB - 1) / TB;

    size_t smem = (96 * 96 + 64 * 97) * sizeof(float);
    cudaFuncSetAttribute(k_gemm, cudaFuncAttributeMaxDynamicSharedMemorySize, (int)smem);

    // graph prep (per launch, deterministic work)
    k_detect<<<1, 32>>>(ei);
    k_extract<<<eb, TB>>>(ei);
    k_zero<<<nb, TB>>>();
    k_count<<<eb, TB>>>();
    k_scanA<<<scan_blocks, 1024>>>();
    k_scanB<<<1, 128>>>(scan_blocks);
    k_scanC<<<scan_blocks, 1024>>>();
    k_scatter<<<eb, TB>>>();

    // layer 1
    k_gemm<<<gemm_blocks, TB, smem>>>(x, W1, h);
    k_alpha<<<warp_blocks, TB>>>(h, a1);
    k_edgew<<<eb, TB>>>();
    k_agg<<<warp_blocks, TB>>>(h, mid, 0);

    // layer 2
    k_gemm<<<gemm_blocks, TB, smem>>>(mid, W2, h);
    k_alpha<<<warp_blocks, TB>>>(h, a2);
    k_edgew<<<eb, TB>>>();
    k_agg<<<warp_blocks, TB>>>(h, out, 1);
}

// round 4
// speedup vs baseline: 1.2019x; 1.2019x over previous
#include <cuda_runtime.h>
#include <cuda_bf16.h>
#include <cstdint>

#define NN 100000
#define EE 800000
#define DD 96

// ---------------- device scratch (allocation-free) ----------------
__device__ float g_h[NN * DD];
__device__ float g_mid[NN * DD];
__device__ float g_alpha_s[NN];
__device__ float g_alpha_d[NN];
__device__ float g_w[EE];
__device__ int   g_src[EE];
__device__ int   g_dst[EE];
__device__ int   g_src_sorted[EE];
__device__ int   g_dst_sorted[EE];
__device__ int   g_counts[NN];
__device__ int   g_cursor[NN];
__device__ int   g_offsets[NN + 1];
__device__ int   g_bsums[128];
__device__ int   g_is64;

__device__ __forceinline__ uint16_t bfbits(float x) {
    __nv_bfloat16 b = __float2bfloat16(x);
    return *reinterpret_cast<uint16_t*>(&b);
}
__device__ __forceinline__ float bfval(uint16_t u) {
    __nv_bfloat16 b = *reinterpret_cast<__nv_bfloat16*>(&u);
    return __bfloat162float(b);
}

// ---------------- edge_index layout detection ----------------
__global__ void k_detect(const int* __restrict__ ei) {
    if (threadIdx.x == 0)
        g_is64 = (ei[1] == 0 && ei[3] == 0 && ei[5] == 0) ? 1 : 0;
}

__global__ void k_zero() {
    int i = blockIdx.x * blockDim.x + threadIdx.x;
    if (i < NN) { g_counts[i] = 0; g_cursor[i] = 0; }
}

// extract + histogram in one pass
__global__ void k_extract(const int* __restrict__ ei) {
    int e = blockIdx.x * blockDim.x + threadIdx.x;
    if (e >= EE) return;
    int s, d;
    if (g_is64) { s = ei[2 * e]; d = ei[2 * (EE + e)]; }
    else        { s = ei[e];     d = ei[EE + e]; }
    g_src[e] = s;
    g_dst[e] = d;
    atomicAdd(&g_counts[s], 1);
}

// ---------------- scan ----------------
__global__ void k_scanA() {
    __shared__ int buf[1024];
    int tid = threadIdx.x;
    int i = blockIdx.x * 1024 + tid;
    int v = (i < NN) ? g_counts[i] : 0;
    buf[tid] = v;
    __syncthreads();
    #pragma unroll
    for (int off = 1; off < 1024; off <<= 1) {
        int t = (tid >= off) ? buf[tid - off] : 0;
        __syncthreads();
        buf[tid] += t;
        __syncthreads();
    }
    if (i < NN) g_offsets[i] = buf[tid] - v;
    if (tid == 1023) g_bsums[blockIdx.x] = buf[1023];
}

__global__ void k_scanB(int nblocks) {
    __shared__ int buf[128];
    int tid = threadIdx.x;
    int v = (tid < nblocks) ? g_bsums[tid] : 0;
    buf[tid] = v;
    __syncthreads();
    #pragma unroll
    for (int off = 1; off < 128; off <<= 1) {
        int t = (tid >= off) ? buf[tid - off] : 0;
        __syncthreads();
        buf[tid] += t;
        __syncthreads();
    }
    if (tid < nblocks) g_bsums[tid] = buf[tid] - v;
}

__global__ void k_scanC() {
    int tid = threadIdx.x;
    int i = blockIdx.x * 1024 + tid;
    if (i < NN) g_offsets[i] += g_bsums[blockIdx.x];
    if (i == 0) g_offsets[NN] = EE;
}

__global__ void k_scatter() {
    int e = blockIdx.x * blockDim.x + threadIdx.x;
    if (e >= EE) return;
    int s = g_src[e];
    int slot = g_offsets[s] + atomicAdd(&g_cursor[s], 1);
    g_dst_sorted[slot] = g_dst[e];
    g_src_sorted[slot] = s;
}

// ---------------- HMMA GEMM + fused alpha ----------------
// H[128x96] = X[128x96] @ W[96x96], bf16 hi/lo split, mma.sync.m16n8k16.
// 8 warps; warp w owns rows [w*16, w*16+16): 12 n-tiles x 6 k-steps x 3 split MMAs.
// smem pitch 52 u32/row => (g,tg) fragment loads land in disjoint bank groups.
#define AP 52

__device__ __forceinline__ void mma16816(float* c, const uint32_t* a, const uint32_t* b) {
    asm volatile(
        "mma.sync.aligned.m16n8k16.row.col.f32.bf16.bf16.f32 "
        "{%0,%1,%2,%3}, {%4,%5,%6,%7}, {%8,%9}, {%0,%1,%2,%3};"
        : "+f"(c[0]), "+f"(c[1]), "+f"(c[2]), "+f"(c[3])
        : "r"(a[0]), "r"(a[1]), "r"(a[2]), "r"(a[3]), "r"(b[0]), "r"(b[1]));
}

static constexpr int SMEM_GEMM = (128 * AP * 2 + 96 * AP * 2) * 4 + 192 * 4;

__global__ void __launch_bounds__(256, 2)
k_gemm_mma(const float* __restrict__ X, const float* __restrict__ W,
           const float* __restrict__ avec, float* __restrict__ H) {
    extern __shared__ uint32_t sm4[];
    uint32_t* Ah = sm4;                  // 128*AP
    uint32_t* Al = Ah + 128 * AP;
    uint32_t* Bh = Al + 128 * AP;        // 96*AP (Wt: row n, k contiguous)
    uint32_t* Bl = Bh + 96 * AP;
    float*    av = (float*)(Bl + 96 * AP);  // 192

    int tid = threadIdx.x, warp = tid >> 5, lane = tid & 31;

    for (int i = tid; i < 192; i += 256) av[i] = avec[i];

    // A tile: thread -> (row = tid>>1, half = tid&1), 48 cols = 24 u32 pairs
    {
        int row = tid >> 1, half = tid & 1;
        long gr = (long)blockIdx.x * 128 + row;
        bool valid = gr < NN;
        const float2* xr = (const float2*)(X + gr * 96 + half * 48);
        uint32_t* ah = Ah + row * AP + half * 24;
        uint32_t* al = Al + row * AP + half * 24;
        #pragma unroll 6
        for (int p = 0; p < 24; p++) {
            float2 v = valid ? xr[p] : make_float2(0.f, 0.f);
            uint16_t h0 = bfbits(v.x), h1 = bfbits(v.y);
            uint16_t l0 = bfbits(v.x - bfval(h0)), l1 = bfbits(v.y - bfval(h1));
            ah[p] = (uint32_t)h0 | ((uint32_t)h1 << 16);
            al[p] = (uint32_t)l0 | ((uint32_t)l1 << 16);
        }
    }

    // B tile: Bt[n][k] = W[k][n]; coalesced read of W, scattered u16 smem writes
    {
        uint16_t* Bhs = (uint16_t*)Bh;
        uint16_t* Bls = (uint16_t*)Bl;
        for (int idx = tid; idx < 96 * 96; idx += 256) {
            int k = idx / 96, n = idx - k * 96;
            float w = W[idx];
            uint16_t h = bfbits(w);
            uint16_t l = bfbits(w - bfval(h));
            Bhs[n * (2 * AP) + k] = h;
            Bls[n * (2 * AP) + k] = l;
        }
    }
    __syncthreads();

    int g = lane >> 2, tg = lane & 3;
    float c[12][4];
    #pragma unroll
    for (int nt = 0; nt < 12; nt++)
        #pragma unroll
        for (int q = 0; q < 4; q++) c[nt][q] = 0.f;

    int ra = warp * 16 + g;       // local rows ra, ra+8
    #pragma unroll
    for (int ks = 0; ks < 6; ks++) {
        int kp = ks * 8;          // k0/2 in u32 units
        uint32_t ah[4], al[4];
        ah[0] = Ah[ra * AP + kp + tg];
        ah[1] = Ah[(ra + 8) * AP + kp + tg];
        ah[2] = Ah[ra * AP + kp + tg + 4];
        ah[3] = Ah[(ra + 8) * AP + kp + tg + 4];
        al[0] = Al[ra * AP + kp + tg];
        al[1] = Al[(ra + 8) * AP + kp + tg];
        al[2] = Al[ra * AP + kp + tg + 4];
        al[3] = Al[(ra + 8) * AP + kp + tg + 4];
        #pragma unroll
        for (int nt = 0; nt < 12; nt++) {
            int col = nt * 8 + g;
            uint32_t bh[2], bl[2];
            bh[0] = Bh[col * AP + kp + tg];
            bh[1] = Bh[col * AP + kp + tg + 4];
            bl[0] = Bl[col * AP + kp + tg];
            bl[1] = Bl[col * AP + kp + tg + 4];
            mma16816(c[nt], ah, bh);
            mma16816(c[nt], ah, bl);
            mma16816(c[nt], al, bh);
        }
    }

    // epilogue: rows r0 = blk*128 + warp*16 + g, r1 = r0 + 8
    long r0 = (long)blockIdx.x * 128 + warp * 16 + g;
    long r1 = r0 + 8;

    float as0 = 0.f, ad0 = 0.f, as1 = 0.f, ad1 = 0.f;
    #pragma unroll
    for (int nt = 0; nt < 12; nt++) {
        int col = nt * 8 + tg * 2;
        float a0 = av[col], a1 = av[col + 1];
        float d0 = av[96 + col], d1 = av[97 + col];
        as0 = fmaf(c[nt][0], a0, fmaf(c[nt][1], a1, as0));
        ad0 = fmaf(c[nt][0], d0, fmaf(c[nt][1], d1, ad0));
        as1 = fmaf(c[nt][2], a0, fmaf(c[nt][3], a1, as1));
        ad1 = fmaf(c[nt][2], d0, fmaf(c[nt][3], d1, ad1));
    }
    #pragma unroll
    for (int o = 1; o <= 2; o <<= 1) {
        as0 += __shfl_xor_sync(0xffffffffu, as0, o);
        ad0 += __shfl_xor_sync(0xffffffffu, ad0, o);
        as1 += __shfl_xor_sync(0xffffffffu, as1, o);
        ad1 += __shfl_xor_sync(0xffffffffu, ad1, o);
    }
    if (tg == 0) {
        if (r0 < NN) { g_alpha_s[r0] = as0; g_alpha_d[r0] = ad0; }
        if (r1 < NN) { g_alpha_s[r1] = as1; g_alpha_d[r1] = ad1; }
    }

    if (r0 < NN) {
        float* o = H + r0 * 96 + tg * 2;
        #pragma unroll
        for (int nt = 0; nt < 12; nt++)
            *(float2*)(o + nt * 8) = make_float2(c[nt][0], c[nt][1]);
    }
    if (r1 < NN) {
        float* o = H + r1 * 96 + tg * 2;
        #pragma unroll
        for (int nt = 0; nt < 12; nt++)
            *(float2*)(o + nt * 8) = make_float2(c[nt][2], c[nt][3]);
    }
}

// ---------------- per-edge weight (CSR order) ----------------
__global__ void k_edgew() {
    int i = blockIdx.x * blockDim.x + threadIdx.x;
    if (i >= EE) return;
    float s = g_alpha_s[g_src_sorted[i]] + g_alpha_d[g_dst_sorted[i]];
    float lr = (s > 0.f) ? s : 0.01f * s;
    g_w[i] = __expf(-lr);
}

// ---------------- aggregation: warp per node ----------------
__global__ void k_agg(const float* __restrict__ h, float* __restrict__ out, int relu) {
    int t = blockIdx.x * blockDim.x + threadIdx.x;
    int n = t >> 5, lane = t & 31;
    if (n >= NN) return;
    int j = g_offsets[n], e = g_offsets[n + 1];
    float aw = 0.f, a0 = 0.f, a1 = 0.f, a2 = 0.f;
    for (; j < e; j++) {
        int d = g_dst_sorted[j];
        float w = g_w[j];
        const float* hr = h + (size_t)d * DD;
        aw += w;
        a0 = fmaf(w, hr[lane], a0);
        a1 = fmaf(w, hr[lane + 32], a1);
        a2 = fmaf(w, hr[lane + 64], a2);
    }
    float inv = 1.0f / aw;
    a0 *= inv; a1 *= inv; a2 *= inv;
    if (relu) { a0 = fmaxf(a0, 0.f); a1 = fmaxf(a1, 0.f); a2 = fmaxf(a2, 0.f); }
    float* o = out + (size_t)n * DD;
    o[lane] = a0; o[lane + 32] = a1; o[lane + 64] = a2;
}

// ---------------- launch ----------------
extern "C" void kernel_launch(void* const* d_in, const int* in_sizes, int n_in,
                              void* d_out, int out_size) {
    const int*   ei = (const int*)d_in[0];
    const float* x  = (const float*)d_in[1];
    const float* W1 = (const float*)d_in[2];
    const float* a1 = (const float*)d_in[3];
    const float* W2 = (const float*)d_in[4];
    const float* a2 = (const float*)d_in[5];
    float* out = (float*)d_out;

    void *ph, *pmid;
    cudaGetSymbolAddress(&ph, g_h);
    cudaGetSymbolAddress(&pmid, g_mid);
    float* h   = (float*)ph;
    float* mid = (float*)pmid;

    const int TB = 256;
    const int eb = (EE + TB - 1) / TB;
    const int nb = (NN + TB - 1) / TB;
    const int scan_blocks = (NN + 1023) / 1024;
    const int mma_blocks = (NN + 127) / 128;      // 782
    const int warp_blocks = (NN * 32 + TB - 1) / TB;

    cudaFuncSetAttribute(k_gemm_mma, cudaFuncAttributeMaxDynamicSharedMemorySize, SMEM_GEMM);

    // CSR build
    k_detect<<<1, 32>>>(ei);
    k_zero<<<nb, TB>>>();
    k_extract<<<eb, TB>>>(ei);
    k_scanA<<<scan_blocks, 1024>>>();
    k_scanB<<<1, 128>>>(scan_blocks);
    k_scanC<<<scan_blocks, 1024>>>();
    k_scatter<<<eb, TB>>>();

    // layer 1
    k_gemm_mma<<<mma_blocks, TB, SMEM_GEMM>>>(x, W1, a1, h);
    k_edgew<<<eb, TB>>>();
    k_agg<<<warp_blocks, TB>>>(h, mid, 0);

    // layer 2
    k_gemm_mma<<<mma_blocks, TB, SMEM_GEMM>>>(mid, W2, a2, h);
    k_edgew<<<eb, TB>>>();
    k_agg<<<warp_blocks, TB>>>(h, out, 1);
}

// round 5
// speedup vs baseline: 1.2287x; 1.0223x over previous
#include <cuda_runtime.h>
#include <cuda_bf16.h>
#include <cstdint>

#define NN 100000
#define EE 800000
#define DD 96

// ---------------- device scratch (allocation-free) ----------------
__device__ float g_h[NN * DD];
__device__ float g_mid[NN * DD];
__device__ float g_alpha_s[NN];
__device__ float g_alpha_d[NN];
__device__ int   g_src[EE];
__device__ int   g_dst_sorted[EE];
__device__ int   g_counts[NN];
__device__ int   g_cursor[NN];
__device__ int   g_offsets[NN + 1];
__device__ int   g_bsums[128];

__device__ __forceinline__ uint16_t bfbits(float x) {
    __nv_bfloat16 b = __float2bfloat16(x);
    return *reinterpret_cast<uint16_t*>(&b);
}
__device__ __forceinline__ float bfval(uint16_t u) {
    __nv_bfloat16 b = *reinterpret_cast<__nv_bfloat16*>(&u);
    return __bfloat162float(b);
}

// ---------------- extract + histogram (layout detect inlined) ----------------
__global__ void k_extract(const int* __restrict__ ei) {
    __shared__ int s_is64;
    if (threadIdx.x == 0)
        s_is64 = (ei[1] == 0 && ei[3] == 0 && ei[5] == 0) ? 1 : 0;
    __syncthreads();
    int e = blockIdx.x * blockDim.x + threadIdx.x;
    if (e >= EE) return;
    int s, d;
    if (s_is64) { s = ei[2 * e]; d = ei[2 * (EE + e)]; }
    else        { s = ei[e];     d = ei[EE + e]; }
    g_src[e] = s;
    g_dst_sorted[e] = d;     // temp: original order; scatter rewrites
    atomicAdd(&g_counts[s], 1);
}

// ---------------- scan: shfl-based block scan ----------------
__global__ void k_scanA() {
    __shared__ int wsum[32];
    int tid = threadIdx.x, lane = tid & 31, w = tid >> 5;
    int i = blockIdx.x * 1024 + tid;
    int v = (i < NN) ? g_counts[i] : 0;
    int x = v;
    #pragma unroll
    for (int o = 1; o < 32; o <<= 1) {
        int t = __shfl_up_sync(0xffffffffu, x, o);
        if (lane >= o) x += t;
    }
    if (lane == 31) wsum[w] = x;
    __syncthreads();
    if (w == 0) {
        int s = wsum[lane];
        #pragma unroll
        for (int o = 1; o < 32; o <<= 1) {
            int t = __shfl_up_sync(0xffffffffu, s, o);
            if (lane >= o) s += t;
        }
        wsum[lane] = s;
    }
    __syncthreads();
    int pre = (w > 0) ? wsum[w - 1] : 0;
    int incl = x + pre;
    if (i < NN) g_offsets[i] = incl - v;       // block-local exclusive
    if (tid == 1023) g_bsums[blockIdx.x] = incl;
}

// add cross-block prefix (each block reduces its own bsums prefix; 98 entries)
__global__ void k_scanC() {
    __shared__ int pre_s;
    int tid = threadIdx.x;
    if (tid < 32) {
        int acc = 0;
        for (int j = tid; j < blockIdx.x; j += 32) acc += g_bsums[j];
        #pragma unroll
        for (int o = 16; o; o >>= 1) acc += __shfl_xor_sync(0xffffffffu, acc, o);
        if (tid == 0) pre_s = acc;
    }
    __syncthreads();
    int i = blockIdx.x * 1024 + tid;
    if (i < NN) g_offsets[i] += pre_s;
    if (i == 0) g_offsets[NN] = EE;
}

// scatter dst into CSR order (reads temp dst from g_dst_sorted via g_src pairing)
__global__ void k_scatter(const int* __restrict__ ei) {
    __shared__ int s_is64;
    if (threadIdx.x == 0)
        s_is64 = (ei[1] == 0 && ei[3] == 0 && ei[5] == 0) ? 1 : 0;
    __syncthreads();
    int e = blockIdx.x * blockDim.x + threadIdx.x;
    if (e >= EE) return;
    int s = g_src[e];
    int d;
    if (s_is64) d = ei[2 * (EE + e)];
    else        d = ei[EE + e];
    int slot = g_offsets[s] + atomicAdd(&g_cursor[s], 1);
    g_dst_sorted[slot] = d;
}

// ---------------- HMMA GEMM + fused alpha ----------------
#define AP 52

__device__ __forceinline__ void mma16816(float* c, const uint32_t* a, const uint32_t* b) {
    asm volatile(
        "mma.sync.aligned.m16n8k16.row.col.f32.bf16.bf16.f32 "
        "{%0,%1,%2,%3}, {%4,%5,%6,%7}, {%8,%9}, {%0,%1,%2,%3};"
        : "+f"(c[0]), "+f"(c[1]), "+f"(c[2]), "+f"(c[3])
        : "r"(a[0]), "r"(a[1]), "r"(a[2]), "r"(a[3]), "r"(b[0]), "r"(b[1]));
}

static constexpr int SMEM_GEMM = (128 * AP * 2 + 96 * AP * 2) * 4 + 192 * 4;

__global__ void __launch_bounds__(256, 2)
k_gemm_mma(const float* __restrict__ X, const float* __restrict__ W,
           const float* __restrict__ avec, float* __restrict__ H) {
    extern __shared__ uint32_t sm4[];
    uint32_t* Ah = sm4;
    uint32_t* Al = Ah + 128 * AP;
    uint32_t* Bh = Al + 128 * AP;
    uint32_t* Bl = Bh + 96 * AP;
    float*    av = (float*)(Bl + 96 * AP);

    int tid = threadIdx.x, warp = tid >> 5, lane = tid & 31;

    for (int i = tid; i < 192; i += 256) av[i] = avec[i];

    // A tile
    {
        int row = tid >> 1, half = tid & 1;
        long gr = (long)blockIdx.x * 128 + row;
        bool valid = gr < NN;
        const float2* xr = (const float2*)(X + gr * 96 + half * 48);
        uint32_t* ah = Ah + row * AP + half * 24;
        uint32_t* al = Al + row * AP + half * 24;
        #pragma unroll 6
        for (int p = 0; p < 24; p++) {
            float2 v = valid ? xr[p] : make_float2(0.f, 0.f);
            uint16_t h0 = bfbits(v.x), h1 = bfbits(v.y);
            uint16_t l0 = bfbits(v.x - bfval(h0)), l1 = bfbits(v.y - bfval(h1));
            ah[p] = (uint32_t)h0 | ((uint32_t)h1 << 16);
            al[p] = (uint32_t)l0 | ((uint32_t)l1 << 16);
        }
    }

    // B tile: Bt[n][k] = W[k][n]
    {
        uint16_t* Bhs = (uint16_t*)Bh;
        uint16_t* Bls = (uint16_t*)Bl;
        for (int idx = tid; idx < 96 * 96; idx += 256) {
            int k = idx / 96, n = idx - k * 96;
            float w = W[idx];
            uint16_t h = bfbits(w);
            uint16_t l = bfbits(w - bfval(h));
            Bhs[n * (2 * AP) + k] = h;
            Bls[n * (2 * AP) + k] = l;
        }
    }
    __syncthreads();

    int g = lane >> 2, tg = lane & 3;
    float c[12][4];
    #pragma unroll
    for (int nt = 0; nt < 12; nt++)
        #pragma unroll
        for (int q = 0; q < 4; q++) c[nt][q] = 0.f;

    int ra = warp * 16 + g;
    #pragma unroll
    for (int ks = 0; ks < 6; ks++) {
        int kp = ks * 8;
        uint32_t ah[4], al[4];
        ah[0] = Ah[ra * AP + kp + tg];
        ah[1] = Ah[(ra + 8) * AP + kp + tg];
        ah[2] = Ah[ra * AP + kp + tg + 4];
        ah[3] = Ah[(ra + 8) * AP + kp + tg + 4];
        al[0] = Al[ra * AP + kp + tg];
        al[1] = Al[(ra + 8) * AP + kp + tg];
        al[2] = Al[ra * AP + kp + tg + 4];
        al[3] = Al[(ra + 8) * AP + kp + tg + 4];
        #pragma unroll
        for (int nt = 0; nt < 12; nt++) {
            int col = nt * 8 + g;
            uint32_t bh[2], bl[2];
            bh[0] = Bh[col * AP + kp + tg];
            bh[1] = Bh[col * AP + kp + tg + 4];
            bl[0] = Bl[col * AP + kp + tg];
            bl[1] = Bl[col * AP + kp + tg + 4];
            mma16816(c[nt], ah, bh);
            mma16816(c[nt], ah, bl);
            mma16816(c[nt], al, bh);
        }
    }

    long r0 = (long)blockIdx.x * 128 + warp * 16 + g;
    long r1 = r0 + 8;

    float as0 = 0.f, ad0 = 0.f, as1 = 0.f, ad1 = 0.f;
    #pragma unroll
    for (int nt = 0; nt < 12; nt++) {
        int col = nt * 8 + tg * 2;
        float a0 = av[col], a1 = av[col + 1];
        float d0 = av[96 + col], d1 = av[97 + col];
        as0 = fmaf(c[nt][0], a0, fmaf(c[nt][1], a1, as0));
        ad0 = fmaf(c[nt][0], d0, fmaf(c[nt][1], d1, ad0));
        as1 = fmaf(c[nt][2], a0, fmaf(c[nt][3], a1, as1));
        ad1 = fmaf(c[nt][2], d0, fmaf(c[nt][3], d1, ad1));
    }
    #pragma unroll
    for (int o = 1; o <= 2; o <<= 1) {
        as0 += __shfl_xor_sync(0xffffffffu, as0, o);
        ad0 += __shfl_xor_sync(0xffffffffu, ad0, o);
        as1 += __shfl_xor_sync(0xffffffffu, as1, o);
        ad1 += __shfl_xor_sync(0xffffffffu, ad1, o);
    }
    if (tg == 0) {
        if (r0 < NN) { g_alpha_s[r0] = as0; g_alpha_d[r0] = ad0; }
        if (r1 < NN) { g_alpha_s[r1] = as1; g_alpha_d[r1] = ad1; }
    }

    if (r0 < NN) {
        float* o = H + r0 * 96 + tg * 2;
        #pragma unroll
        for (int nt = 0; nt < 12; nt++)
            *(float2*)(o + nt * 8) = make_float2(c[nt][0], c[nt][1]);
    }
    if (r1 < NN) {
        float* o = H + r1 * 96 + tg * 2;
        #pragma unroll
        for (int nt = 0; nt < 12; nt++)
            *(float2*)(o + nt * 8) = make_float2(c[nt][2], c[nt][3]);
    }
}

// ---------------- fused edge-weight + aggregation: warp per node ----------------
// lane-parallel weight computation (one exp per edge per warp), then
// 2-way unrolled gather with shfl-broadcast of (dst, w).
__global__ void k_agg(const float* __restrict__ h, float* __restrict__ out, int relu) {
    int t = blockIdx.x * blockDim.x + threadIdx.x;
    int n = t >> 5, lane = t & 31;
    if (n >= NN) return;
    int j0 = g_offsets[n];
    int cnt = g_offsets[n + 1] - j0;
    float asn = g_alpha_s[n];

    float aw = 0.f, a0 = 0.f, a1 = 0.f, a2 = 0.f;

    for (int base = 0; base < cnt; base += 32) {
        int m = cnt - base; if (m > 32) m = 32;
        int dl = 0; float wl = 0.f;
        if (lane < m) {
            dl = g_dst_sorted[j0 + base + lane];
            float s = asn + g_alpha_d[dl];
            float lr = (s > 0.f) ? s : 0.01f * s;
            wl = __expf(-lr);
        }
        int e = 0;
        for (; e + 1 < m; e += 2) {
            int   d0 = __shfl_sync(0xffffffffu, dl, e);
            int   d1 = __shfl_sync(0xffffffffu, dl, e + 1);
            float w0 = __shfl_sync(0xffffffffu, wl, e);
            float w1 = __shfl_sync(0xffffffffu, wl, e + 1);
            const float* h0 = h + (size_t)d0 * DD;
            const float* h1 = h + (size_t)d1 * DD;
            float x00 = h0[lane], x01 = h0[lane + 32], x02 = h0[lane + 64];
            float x10 = h1[lane], x11 = h1[lane + 32], x12 = h1[lane + 64];
            aw += w0 + w1;
            a0 = fmaf(w0, x00, fmaf(w1, x10, a0));
            a1 = fmaf(w0, x01, fmaf(w1, x11, a1));
            a2 = fmaf(w0, x02, fmaf(w1, x12, a2));
        }
        if (e < m) {
            int   d0 = __shfl_sync(0xffffffffu, dl, e);
            float w0 = __shfl_sync(0xffffffffu, wl, e);
            const float* h0 = h + (size_t)d0 * DD;
            aw += w0;
            a0 = fmaf(w0, h0[lane], a0);
            a1 = fmaf(w0, h0[lane + 32], a1);
            a2 = fmaf(w0, h0[lane + 64], a2);
        }
    }

    float inv = 1.0f / aw;
    a0 *= inv; a1 *= inv; a2 *= inv;
    if (relu) { a0 = fmaxf(a0, 0.f); a1 = fmaxf(a1, 0.f); a2 = fmaxf(a2, 0.f); }
    float* o = out + (size_t)n * DD;
    o[lane] = a0; o[lane + 32] = a1; o[lane + 64] = a2;
}

// ---------------- launch ----------------
extern "C" void kernel_launch(void* const* d_in, const int* in_sizes, int n_in,
                              void* d_out, int out_size) {
    const int*   ei = (const int*)d_in[0];
    const float* x  = (const float*)d_in[1];
    const float* W1 = (const float*)d_in[2];
    const float* a1 = (const float*)d_in[3];
    const float* W2 = (const float*)d_in[4];
    const float* a2 = (const float*)d_in[5];
    float* out = (float*)d_out;

    void *ph, *pmid, *pcnt, *pcur;
    cudaGetSymbolAddress(&ph, g_h);
    cudaGetSymbolAddress(&pmid, g_mid);
    cudaGetSymbolAddress(&pcnt, g_counts);
    cudaGetSymbolAddress(&pcur, g_cursor);
    float* h   = (float*)ph;
    float* mid = (float*)pmid;

    const int TB = 256;
    const int eb = (EE + TB - 1) / TB;
    const int scan_blocks = (NN + 1023) / 1024;
    const int mma_blocks = (NN + 127) / 128;
    const int warp_blocks = (NN * 32 + TB - 1) / TB;

    cudaFuncSetAttribute(k_gemm_mma, cudaFuncAttributeMaxDynamicSharedMemorySize, SMEM_GEMM);

    // CSR build
    cudaMemsetAsync(pcnt, 0, NN * sizeof(int));
    cudaMemsetAsync(pcur, 0, NN * sizeof(int));
    k_extract<<<eb, TB>>>(ei);
    k_scanA<<<scan_blocks, 1024>>>();
    k_scanC<<<scan_blocks, 1024>>>();
    k_scatter<<<eb, TB>>>(ei);

    // layer 1
    k_gemm_mma<<<mma_blocks, TB, SMEM_GEMM>>>(x, W1, a1, h);
    k_agg<<<warp_blocks, TB>>>(h, mid, 0);

    // layer 2
    k_gemm_mma<<<mma_blocks, TB, SMEM_GEMM>>>(mid, W2, a2, h);
    k_agg<<<warp_blocks, TB>>>(h, out, 1);
}